// round 1
// baseline (speedup 1.0000x reference)
#include <cuda_runtime.h>
#include <cuda_bf16.h>

// SSIM loss, fused single-pass tiled kernel.
// sr, hr: [16,3,512,512] fp32. Crop 10px -> [492,492] Y images, 11x11 box
// filters (zero-padded), SSIM map, sum(1-ssim)/batch.

#define IMG   512
#define CROP  492          // 512 - 2*10
#define SHAVE 10
#define TILE  32
#define HALO  5
#define TW    42           // TILE + 2*HALO
#define TSTR  43           // smem stride (odd, conflict-free)
#define NTHREADS 256

__device__ double g_ssim_sum;

__global__ void zero_accum_kernel() { g_ssim_sum = 0.0; }

__global__ __launch_bounds__(NTHREADS)
void ssim_tile_kernel(const float* __restrict__ sr, const float* __restrict__ hr)
{
    __shared__ float s_a[TW * TSTR];          // Y(sr) tile with halo
    __shared__ float s_b[TW * TSTR];          // Y(hr) tile with halo
    __shared__ float cs_a[TILE * TSTR];       // 11-row column sums
    __shared__ float cs_b[TILE * TSTR];
    __shared__ float cs_aa[TILE * TSTR];
    __shared__ float cs_bb[TILE * TSTR];
    __shared__ float cs_ab[TILE * TSTR];
    __shared__ float red[NTHREADS / 32];

    const int tid = threadIdx.x;
    const int n   = blockIdx.z;
    const int oy0 = blockIdx.y * TILE;
    const int ox0 = blockIdx.x * TILE;

    const float w0 = 65.738f  / 256.0f;
    const float w1 = 129.057f / 256.0f;
    const float w2 = 25.064f  / 256.0f;
    const float inv255 = 1.0f / 255.0f;

    const float* sa0 = sr + (size_t)n * 3 * IMG * IMG;
    const float* sb0 = hr + (size_t)n * 3 * IMG * IMG;

    // ---- Phase 1: load halo tile, fuse normalize + RGB->Y ----
    for (int idx = tid; idx < TW * TW; idx += NTHREADS) {
        int ry = idx / TW, rx = idx % TW;
        int gy = oy0 + ry - HALO;
        int gx = ox0 + rx - HALO;
        float a = 0.0f, b = 0.0f;
        if (gy >= 0 && gy < CROP && gx >= 0 && gx < CROP) {
            int base = (gy + SHAVE) * IMG + (gx + SHAVE);
            float c0 = fminf(fmaxf(sa0[base]                 * inv255, 0.0f), 1.0f);
            float c1 = fminf(fmaxf(sa0[IMG*IMG + base]       * inv255, 0.0f), 1.0f);
            float c2 = fminf(fmaxf(sa0[2*IMG*IMG + base]     * inv255, 0.0f), 1.0f);
            a = w0 * c0 + w1 * c1 + w2 * c2;
            float d0 = fminf(fmaxf(sb0[base]                 * inv255, 0.0f), 1.0f);
            float d1 = fminf(fmaxf(sb0[IMG*IMG + base]       * inv255, 0.0f), 1.0f);
            float d2 = fminf(fmaxf(sb0[2*IMG*IMG + base]     * inv255, 0.0f), 1.0f);
            b = w0 * d0 + w1 * d1 + w2 * d2;
        }
        s_a[ry * TSTR + rx] = a;
        s_b[ry * TSTR + rx] = b;
    }
    __syncthreads();

    // ---- Phase 2: vertical 11-tap column sums for the 5 quantities ----
    for (int idx = tid; idx < TILE * TW; idx += NTHREADS) {
        int yo = idx / TW, x = idx % TW;
        float sa = 0.f, sb = 0.f, saa = 0.f, sbb = 0.f, sab = 0.f;
        #pragma unroll
        for (int dy = 0; dy < 11; dy++) {
            float a = s_a[(yo + dy) * TSTR + x];
            float b = s_b[(yo + dy) * TSTR + x];
            sa += a; sb += b;
            saa += a * a; sbb += b * b; sab += a * b;
        }
        cs_a[yo * TSTR + x]  = sa;
        cs_b[yo * TSTR + x]  = sb;
        cs_aa[yo * TSTR + x] = saa;
        cs_bb[yo * TSTR + x] = sbb;
        cs_ab[yo * TSTR + x] = sab;
    }
    __syncthreads();

    // ---- Phase 3: horizontal 11-tap sums + SSIM + accumulate ----
    const float inv121 = 1.0f / 121.0f;
    const float C1 = 6.5025f;    // (0.01*255)^2
    const float C2 = 58.5225f;   // (0.03*255)^2

    float acc = 0.0f;
    for (int idx = tid; idx < TILE * TILE; idx += NTHREADS) {
        int yo = idx / TILE, xo = idx % TILE;
        int gy = oy0 + yo, gx = ox0 + xo;
        if (gy < CROP && gx < CROP) {
            float Sa = 0.f, Sb = 0.f, Saa = 0.f, Sbb = 0.f, Sab = 0.f;
            #pragma unroll
            for (int dx = 0; dx < 11; dx++) {
                int o = yo * TSTR + xo + dx;
                Sa  += cs_a[o];
                Sb  += cs_b[o];
                Saa += cs_aa[o];
                Sbb += cs_bb[o];
                Sab += cs_ab[o];
            }
            float mu1 = Sa * inv121;
            float mu2 = Sb * inv121;
            float mu1_sq  = mu1 * mu1;
            float mu2_sq  = mu2 * mu2;
            float mu1_mu2 = mu1 * mu2;
            float sigma1 = Saa * inv121 - mu1_sq;
            float sigma2 = Sbb * inv121 - mu2_sq;
            float sigma12 = Sab * inv121 - mu1_mu2;
            float num = (2.0f * mu1_mu2 + C1) * (2.0f * sigma12 + C2);
            float den = (mu1_sq + mu2_sq + C1) * (sigma1 + sigma2 + C2);
            acc += 1.0f - num / den;
        }
    }

    // ---- block reduction ----
    #pragma unroll
    for (int off = 16; off > 0; off >>= 1)
        acc += __shfl_down_sync(0xffffffffu, acc, off);
    int lane = tid & 31, warp = tid >> 5;
    if (lane == 0) red[warp] = acc;
    __syncthreads();
    if (warp == 0) {
        float v = (lane < NTHREADS / 32) ? red[lane] : 0.0f;
        #pragma unroll
        for (int off = 16; off > 0; off >>= 1)
            v += __shfl_down_sync(0xffffffffu, v, off);
        if (lane == 0)
            atomicAdd(&g_ssim_sum, (double)v);
    }
}

__global__ void finalize_kernel(float* __restrict__ out, const void* __restrict__ bs_ptr)
{
    float divisor = 16.0f;
    if (bs_ptr) {
        int vi = *(const int*)bs_ptr;
        if (vi > 0 && vi < 100000000) divisor = (float)vi;
        else {
            float vf = *(const float*)bs_ptr;
            if (vf > 0.0f && vf < 1.0e8f) divisor = vf;
        }
    }
    out[0] = (float)(g_ssim_sum / (double)divisor);
}

extern "C" void kernel_launch(void* const* d_in, const int* in_sizes, int n_in,
                              void* d_out, int out_size)
{
    const float* sr = (const float*)d_in[0];
    const float* hr = (const float*)d_in[1];
    const void* bs  = (n_in >= 3) ? d_in[2] : nullptr;
    float* out = (float*)d_out;

    zero_accum_kernel<<<1, 1>>>();

    dim3 grid((CROP + TILE - 1) / TILE,   // 16
              (CROP + TILE - 1) / TILE,   // 16
              16);                        // batch
    ssim_tile_kernel<<<grid, NTHREADS>>>(sr, hr);

    finalize_kernel<<<1, 1>>>(out, bs);
}

// round 2
// speedup vs baseline: 1.6210x; 1.6210x over previous
#include <cuda_runtime.h>
#include <cuda_bf16.h>

// SSIM loss — band-structured fused kernel.
// Each block = (image, horizontal band of 28 output rows) covering the full
// 492-col width. One thread per column; vertical 11-tap box sums kept as
// register sliding windows; only 5 column-sum planes hit smem; horizontal
// 11-tap via conflict-free swizzled sliding windows (runs of 4).

#define IMG    512
#define CROP   492
#define SHAVE  10
#define PLANE  (IMG * IMG)

#define NBANDS 18
#define RROWS  28          // output rows per band (18*28 = 504 >= 492)
#define GROWS  4           // output rows buffered per horizontal batch
#define NBATCH (RROWS / GROWS)   // 7
#define WID    576         // swizzled row capacity (max logical idx 503 -> 565)
#define NT     512

#define SWZ(i) ((i) + ((i) >> 3))
#define CSI(q, s, i) ((((q) << 2) + (s)) * WID + SWZ(i))

__device__ double g_part[NBANDS * 16];

__device__ __forceinline__ void insert_row(
    const float* __restrict__ A, const float* __restrict__ B, int off, bool valid,
    float (&wa)[11], float (&wb)[11],
    float& Sa, float& Sb, float& Saa, float& Sbb, float& Sab)
{
    const float w0 = 65.738f  / 256.0f;
    const float w1 = 129.057f / 256.0f;
    const float w2 = 25.064f  / 256.0f;
    const float inv255 = 1.0f / 255.0f;

    float a = 0.0f, b = 0.0f;
    if (valid) {
        float c0 = fminf(fmaxf(A[off]            * inv255, 0.0f), 1.0f);
        float c1 = fminf(fmaxf(A[off + PLANE]    * inv255, 0.0f), 1.0f);
        float c2 = fminf(fmaxf(A[off + 2*PLANE]  * inv255, 0.0f), 1.0f);
        a = w0 * c0 + w1 * c1 + w2 * c2;
        float d0 = fminf(fmaxf(B[off]            * inv255, 0.0f), 1.0f);
        float d1 = fminf(fmaxf(B[off + PLANE]    * inv255, 0.0f), 1.0f);
        float d2 = fminf(fmaxf(B[off + 2*PLANE]  * inv255, 0.0f), 1.0f);
        b = w0 * d0 + w1 * d1 + w2 * d2;
    }
    float oa = wa[0], ob = wb[0];
    Sa  += a - oa;
    Sb  += b - ob;
    Saa += a * a - oa * oa;
    Sbb += b * b - ob * ob;
    Sab += a * b - oa * ob;
    #pragma unroll
    for (int k = 0; k < 10; k++) { wa[k] = wa[k + 1]; wb[k] = wb[k + 1]; }
    wa[10] = a; wb[10] = b;
}

__global__ __launch_bounds__(NT, 2)
void ssim_band_kernel(const float* __restrict__ sr, const float* __restrict__ hr)
{
    __shared__ float cs[5 * GROWS * WID];   // 46080 B
    __shared__ float red[NT / 32];

    const int t    = threadIdx.x;
    const int band = blockIdx.x;
    const int n    = blockIdx.y;
    const int oy0  = band * RROWS;

    const float* A = sr + (size_t)n * 3 * PLANE;
    const float* B = hr + (size_t)n * 3 * PLANE;

    // zero entire colsum smem (halo entries stay zero forever)
    for (int i = t; i < 5 * GROWS * WID; i += NT) cs[i] = 0.0f;

    float wa[11], wb[11];
    #pragma unroll
    for (int k = 0; k < 11; k++) { wa[k] = 0.0f; wb[k] = 0.0f; }
    float Sa = 0.f, Sb = 0.f, Saa = 0.f, Sbb = 0.f, Sab = 0.f;

    const bool col_ok = (t < CROP);
    int ry  = oy0 - 5;                       // first Y-image row to insert
    int off = (ry + SHAVE) * IMG + (t + SHAVE);

    // ---- warm-up: insert 10 rows ----
    for (int i = 0; i < 10; i++) {
        bool valid = col_ok && (ry >= 0) && (ry < CROP);
        insert_row(A, B, off, valid, wa, wb, Sa, Sb, Saa, Sbb, Sab);
        ry++; off += IMG;
    }
    __syncthreads();   // cs zero-fill visible

    const float inv121 = 1.0f / 121.0f;
    const float C1 = 6.5025f;
    const float C2 = 58.5225f;

    float acc = 0.0f;

    for (int jb = 0; jb < NBATCH; jb++) {
        // ---- vertical: insert GROWS rows, emit colsums ----
        #pragma unroll
        for (int g = 0; g < GROWS; g++) {
            int gy = oy0 + jb * GROWS + g;
            bool valid = col_ok && (ry < CROP);   // ry = gy+5 >= 0 always
            insert_row(A, B, off, valid, wa, wb, Sa, Sb, Saa, Sbb, Sab);
            ry++; off += IMG;
            if (col_ok && gy < CROP) {
                int ix = t + 5;
                cs[CSI(0, g, ix)] = Sa;
                cs[CSI(1, g, ix)] = Sb;
                cs[CSI(2, g, ix)] = Saa;
                cs[CSI(3, g, ix)] = Sbb;
                cs[CSI(4, g, ix)] = Sab;
            }
        }
        __syncthreads();

        // ---- horizontal: runs of 4 outputs, sliding windows ----
        if (t < 492) {
            int row = t / 123;            // 0..3
            int run = t % 123;
            int x0  = run * 4;
            int gy  = oy0 + jb * GROWS + row;
            if (gy < CROP) {
                float H0 = 0.f, H1 = 0.f, H2 = 0.f, H3 = 0.f, H4 = 0.f;
                #pragma unroll
                for (int d = 0; d < 11; d++) {
                    int ix = x0 + d;
                    H0 += cs[CSI(0, row, ix)];
                    H1 += cs[CSI(1, row, ix)];
                    H2 += cs[CSI(2, row, ix)];
                    H3 += cs[CSI(3, row, ix)];
                    H4 += cs[CSI(4, row, ix)];
                }
                #pragma unroll
                for (int m = 0; m < 4; m++) {
                    float mu1 = H0 * inv121;
                    float mu2 = H1 * inv121;
                    float mu1_sq  = mu1 * mu1;
                    float mu2_sq  = mu2 * mu2;
                    float mu1_mu2 = mu1 * mu2;
                    float sig1  = H2 * inv121 - mu1_sq;
                    float sig2  = H3 * inv121 - mu2_sq;
                    float sig12 = H4 * inv121 - mu1_mu2;
                    float num = (2.0f * mu1_mu2 + C1) * (2.0f * sig12 + C2);
                    float den = (mu1_sq + mu2_sq + C1) * (sig1 + sig2 + C2);
                    acc += 1.0f - __fdividef(num, den);
                    if (m < 3) {
                        int xo = x0 + m;
                        H0 += cs[CSI(0, row, xo + 11)] - cs[CSI(0, row, xo)];
                        H1 += cs[CSI(1, row, xo + 11)] - cs[CSI(1, row, xo)];
                        H2 += cs[CSI(2, row, xo + 11)] - cs[CSI(2, row, xo)];
                        H3 += cs[CSI(3, row, xo + 11)] - cs[CSI(3, row, xo)];
                        H4 += cs[CSI(4, row, xo + 11)] - cs[CSI(4, row, xo)];
                    }
                }
            }
        }
        __syncthreads();
    }

    // ---- block reduction -> per-block partial ----
    #pragma unroll
    for (int o = 16; o > 0; o >>= 1)
        acc += __shfl_down_sync(0xffffffffu, acc, o);
    int lane = t & 31, warp = t >> 5;
    if (lane == 0) red[warp] = acc;
    __syncthreads();
    if (warp == 0) {
        float v = (lane < NT / 32) ? red[lane] : 0.0f;
        #pragma unroll
        for (int o = 16; o > 0; o >>= 1)
            v += __shfl_down_sync(0xffffffffu, v, o);
        if (lane == 0)
            g_part[n * NBANDS + band] = (double)v;
    }
}

__global__ void finalize_kernel(float* __restrict__ out, const void* __restrict__ bs_ptr)
{
    __shared__ double red[16];
    int t = threadIdx.x;
    double v = (t < NBANDS * 16) ? g_part[t] : 0.0;
    #pragma unroll
    for (int o = 16; o > 0; o >>= 1)
        v += __shfl_down_sync(0xffffffffu, v, o);
    int lane = t & 31, warp = t >> 5;
    if (lane == 0) red[warp] = v;
    __syncthreads();
    if (warp == 0) {
        double s = (lane < 16) ? red[lane] : 0.0;
        #pragma unroll
        for (int o = 16; o > 0; o >>= 1)
            s += __shfl_down_sync(0xffffffffu, s, o);
        if (lane == 0) {
            float divisor = 16.0f;
            if (bs_ptr) {
                int vi = *(const int*)bs_ptr;
                if (vi > 0 && vi < 100000000) divisor = (float)vi;
                else {
                    float vf = *(const float*)bs_ptr;
                    if (vf > 0.0f && vf < 1.0e8f) divisor = vf;
                }
            }
            out[0] = (float)(s / (double)divisor);
        }
    }
}

extern "C" void kernel_launch(void* const* d_in, const int* in_sizes, int n_in,
                              void* d_out, int out_size)
{
    const float* sr = (const float*)d_in[0];
    const float* hr = (const float*)d_in[1];
    const void* bs  = (n_in >= 3) ? d_in[2] : nullptr;
    float* out = (float*)d_out;

    dim3 grid(NBANDS, 16);
    ssim_band_kernel<<<grid, NT>>>(sr, hr);
    finalize_kernel<<<1, 512>>>(out, bs);
}

// round 3
// speedup vs baseline: 2.1387x; 1.3193x over previous
#include <cuda_runtime.h>
#include <cuda_bf16.h>

// SSIM loss — band-structured fused kernel, single launch.
// Each block = (image, band of 28 output rows) over full 492-col width.
// One thread per column; vertical 11-tap box sums via register sliding
// windows (fully unrolled -> pure register renaming); horizontal 11-tap via
// swizzled smem sliding windows; last block performs the global reduction.

#define IMG    512
#define CROP   492
#define SHAVE  10
#define PLANE  (IMG * IMG)

#define NBANDS 18
#define RROWS  28
#define GROWS  4
#define NBATCH (RROWS / GROWS)   // 7
#define WID    576
#define NT     512
#define NBLOCKS (NBANDS * 16)    // 288

#define SWZ(i) ((i) + ((i) >> 3))
#define CSI(q, s, i) ((((q) << 2) + (s)) * WID + SWZ(i))

__device__ double   g_part[NBLOCKS];
__device__ unsigned g_count = 0;

__device__ __forceinline__ void insert_row(
    const float* __restrict__ A, const float* __restrict__ B, int off, bool valid,
    float (&wa)[11], float (&wb)[11],
    float& Sa, float& Sb, float& Saa, float& Sbb, float& Sab)
{
    const float w0 = 65.738f  / 256.0f;
    const float w1 = 129.057f / 256.0f;
    const float w2 = 25.064f  / 256.0f;
    const float inv255 = 1.0f / 255.0f;

    float a = 0.0f, b = 0.0f;
    if (valid) {
        float c0 = __saturatef(A[off]           * inv255);
        float c1 = __saturatef(A[off + PLANE]   * inv255);
        float c2 = __saturatef(A[off + 2*PLANE] * inv255);
        a = w0 * c0 + w1 * c1 + w2 * c2;
        float d0 = __saturatef(B[off]           * inv255);
        float d1 = __saturatef(B[off + PLANE]   * inv255);
        float d2 = __saturatef(B[off + 2*PLANE] * inv255);
        b = w0 * d0 + w1 * d1 + w2 * d2;
    }
    float oa = wa[0], ob = wb[0];
    Sa  += a - oa;
    Sb  += b - ob;
    Saa += a * a - oa * oa;
    Sbb += b * b - ob * ob;
    Sab += a * b - oa * ob;
    #pragma unroll
    for (int k = 0; k < 10; k++) { wa[k] = wa[k + 1]; wb[k] = wb[k + 1]; }
    wa[10] = a; wb[10] = b;
}

__global__ __launch_bounds__(NT, 2)
void ssim_band_kernel(const float* __restrict__ sr, const float* __restrict__ hr,
                      float* __restrict__ out, const void* __restrict__ bs_ptr)
{
    __shared__ float  cs[5 * GROWS * WID];   // 46080 B
    __shared__ float  redf[NT / 32];
    __shared__ double redd[NT / 32];
    __shared__ int    s_last;

    const int t    = threadIdx.x;
    const int band = blockIdx.x;
    const int n    = blockIdx.y;
    const int oy0  = band * RROWS;

    const float* A = sr + (size_t)n * 3 * PLANE;
    const float* B = hr + (size_t)n * 3 * PLANE;

    for (int i = t; i < 5 * GROWS * WID; i += NT) cs[i] = 0.0f;

    float wa[11], wb[11];
    #pragma unroll
    for (int k = 0; k < 11; k++) { wa[k] = 0.0f; wb[k] = 0.0f; }
    float Sa = 0.f, Sb = 0.f, Saa = 0.f, Sbb = 0.f, Sab = 0.f;

    const bool col_ok = (t < CROP);
    int ry  = oy0 - 5;
    int off = (ry + SHAVE) * IMG + (t + SHAVE);

    // ---- warm-up: 10 row inserts (fully unrolled -> static window idx) ----
    #pragma unroll
    for (int i = 0; i < 10; i++) {
        bool valid = col_ok && (ry >= 0) && (ry < CROP);
        insert_row(A, B, off, valid, wa, wb, Sa, Sb, Saa, Sbb, Sab);
        ry++; off += IMG;
    }
    __syncthreads();

    const float inv121 = 1.0f / 121.0f;
    const float C1 = 6.5025f;
    const float C2 = 58.5225f;

    float acc = 0.0f;

    #pragma unroll
    for (int jb = 0; jb < NBATCH; jb++) {
        // ---- vertical: insert GROWS rows, emit 5 colsum planes ----
        #pragma unroll
        for (int g = 0; g < GROWS; g++) {
            int gy = oy0 + jb * GROWS + g;
            bool valid = col_ok && (ry < CROP);
            insert_row(A, B, off, valid, wa, wb, Sa, Sb, Saa, Sbb, Sab);
            ry++; off += IMG;
            if (col_ok && gy < CROP) {
                int ix = t + 5;
                cs[CSI(0, g, ix)] = Sa;
                cs[CSI(1, g, ix)] = Sb;
                cs[CSI(2, g, ix)] = Saa;
                cs[CSI(3, g, ix)] = Sbb;
                cs[CSI(4, g, ix)] = Sab;
            }
        }
        __syncthreads();

        // ---- horizontal: runs of 4 outputs, sliding windows ----
        if (t < 492) {
            int row = t / 123;
            int run = t % 123;
            int x0  = run * 4;
            int gy  = oy0 + jb * GROWS + row;
            if (gy < CROP) {
                float H0 = 0.f, H1 = 0.f, H2 = 0.f, H3 = 0.f, H4 = 0.f;
                #pragma unroll
                for (int d = 0; d < 11; d++) {
                    int ix = x0 + d;
                    H0 += cs[CSI(0, row, ix)];
                    H1 += cs[CSI(1, row, ix)];
                    H2 += cs[CSI(2, row, ix)];
                    H3 += cs[CSI(3, row, ix)];
                    H4 += cs[CSI(4, row, ix)];
                }
                #pragma unroll
                for (int m = 0; m < 4; m++) {
                    float mu1 = H0 * inv121;
                    float mu2 = H1 * inv121;
                    float mu1_sq  = mu1 * mu1;
                    float mu2_sq  = mu2 * mu2;
                    float mu1_mu2 = mu1 * mu2;
                    float sig1  = H2 * inv121 - mu1_sq;
                    float sig2  = H3 * inv121 - mu2_sq;
                    float sig12 = H4 * inv121 - mu1_mu2;
                    float num = (2.0f * mu1_mu2 + C1) * (2.0f * sig12 + C2);
                    float den = (mu1_sq + mu2_sq + C1) * (sig1 + sig2 + C2);
                    acc += 1.0f - __fdividef(num, den);
                    if (m < 3) {
                        int xo = x0 + m;
                        H0 += cs[CSI(0, row, xo + 11)] - cs[CSI(0, row, xo)];
                        H1 += cs[CSI(1, row, xo + 11)] - cs[CSI(1, row, xo)];
                        H2 += cs[CSI(2, row, xo + 11)] - cs[CSI(2, row, xo)];
                        H3 += cs[CSI(3, row, xo + 11)] - cs[CSI(3, row, xo)];
                        H4 += cs[CSI(4, row, xo + 11)] - cs[CSI(4, row, xo)];
                    }
                }
            }
        }
        __syncthreads();
    }

    // ---- block reduction -> per-block partial ----
    #pragma unroll
    for (int o = 16; o > 0; o >>= 1)
        acc += __shfl_down_sync(0xffffffffu, acc, o);
    int lane = t & 31, warp = t >> 5;
    if (lane == 0) redf[warp] = acc;
    __syncthreads();
    if (warp == 0) {
        float v = (lane < NT / 32) ? redf[lane] : 0.0f;
        #pragma unroll
        for (int o = 16; o > 0; o >>= 1)
            v += __shfl_down_sync(0xffffffffu, v, o);
        if (lane == 0)
            g_part[n * NBANDS + band] = (double)v;
    }

    // ---- last block performs the global reduction (fence+counter) ----
    if (t == 0) {
        __threadfence();
        unsigned old = atomicAdd(&g_count, 1u);
        s_last = (old == NBLOCKS - 1) ? 1 : 0;
    }
    __syncthreads();
    if (s_last) {
        double v = (t < NBLOCKS) ? g_part[t] : 0.0;
        #pragma unroll
        for (int o = 16; o > 0; o >>= 1)
            v += __shfl_down_sync(0xffffffffu, v, o);
        if (lane == 0) redd[warp] = v;
        __syncthreads();
        if (warp == 0) {
            double s = (lane < NT / 32) ? redd[lane] : 0.0;
            #pragma unroll
            for (int o = 16; o > 0; o >>= 1)
                s += __shfl_down_sync(0xffffffffu, s, o);
            if (lane == 0) {
                float divisor = 16.0f;
                if (bs_ptr) {
                    int vi = *(const int*)bs_ptr;
                    if (vi > 0 && vi < 100000000) divisor = (float)vi;
                    else {
                        float vf = *(const float*)bs_ptr;
                        if (vf > 0.0f && vf < 1.0e8f) divisor = vf;
                    }
                }
                out[0]  = (float)(s / (double)divisor);
                g_count = 0;   // reset for next graph replay
            }
        }
    }
}

extern "C" void kernel_launch(void* const* d_in, const int* in_sizes, int n_in,
                              void* d_out, int out_size)
{
    const float* sr = (const float*)d_in[0];
    const float* hr = (const float*)d_in[1];
    const void* bs  = (n_in >= 3) ? d_in[2] : nullptr;
    float* out = (float*)d_out;

    dim3 grid(NBANDS, 16);
    ssim_band_kernel<<<grid, NT>>>(sr, hr, out, bs);
}

// round 4
// speedup vs baseline: 2.2647x; 1.0589x over previous
#include <cuda_runtime.h>
#include <cuda_bf16.h>

// SSIM loss — band-structured fused kernel, single launch, vectorized smem.
// float4 plane holds (Sa,Sb,Saa,Sbb) column sums, scalar plane holds Sab.
// Vertical 11-tap via register sliding windows; horizontal 11-tap via
// swizzled smem sliding windows in runs of 8 outputs per thread.

#define IMG    512
#define CROP   492
#define SHAVE  10
#define PLANE  (IMG * IMG)

#define NBANDS 16
#define RROWS  32
#define GROWS  8
#define NBATCH (RROWS / GROWS)   // 4
#define WID4   512
#define WIDS   576
#define NT     512
#define NBLOCKS (NBANDS * 16)    // 256

#define SWZ4(i) ((i) ^ (((i) >> 3) & 7))
#define SWZS(i) ((i) + ((i) >> 3))
#define Q4(s, i) ((s) * WID4 + SWZ4(i))
#define Q1(s, i) ((s) * WIDS + SWZS(i))

#define SMEM_BYTES (GROWS * WID4 * 16 + GROWS * WIDS * 4)   // 83968

__device__ double   g_part[NBLOCKS];
__device__ unsigned g_count = 0;

__device__ __forceinline__ void insert_row(
    const float* __restrict__ A, const float* __restrict__ B, int off, bool valid,
    float (&wa)[11], float (&wb)[11],
    float& Sa, float& Sb, float& Saa, float& Sbb, float& Sab)
{
    const float w0 = 65.738f  / 256.0f;
    const float w1 = 129.057f / 256.0f;
    const float w2 = 25.064f  / 256.0f;
    const float inv255 = 1.0f / 255.0f;

    float a = 0.0f, b = 0.0f;
    if (valid) {
        float c0 = __saturatef(A[off]           * inv255);
        float c1 = __saturatef(A[off + PLANE]   * inv255);
        float c2 = __saturatef(A[off + 2*PLANE] * inv255);
        a = w0 * c0 + w1 * c1 + w2 * c2;
        float d0 = __saturatef(B[off]           * inv255);
        float d1 = __saturatef(B[off + PLANE]   * inv255);
        float d2 = __saturatef(B[off + 2*PLANE] * inv255);
        b = w0 * d0 + w1 * d1 + w2 * d2;
    }
    float oa = wa[0], ob = wb[0];
    Sa  += a - oa;
    Sb  += b - ob;
    Saa += a * a - oa * oa;
    Sbb += b * b - ob * ob;
    Sab += a * b - oa * ob;
    #pragma unroll
    for (int k = 0; k < 10; k++) { wa[k] = wa[k + 1]; wb[k] = wb[k + 1]; }
    wa[10] = a; wb[10] = b;
}

__global__ __launch_bounds__(NT, 2)
void ssim_band_kernel(const float* __restrict__ sr, const float* __restrict__ hr,
                      float* __restrict__ out, const void* __restrict__ bs_ptr)
{
    extern __shared__ char smem_raw[];
    float4* cs4 = (float4*)smem_raw;                              // [GROWS][WID4]
    float*  cs1 = (float*)(smem_raw + GROWS * WID4 * 16);          // [GROWS][WIDS]

    __shared__ float  redf[NT / 32];
    __shared__ double redd[NT / 32];
    __shared__ int    s_last;

    const int t    = threadIdx.x;
    const int band = blockIdx.x;
    const int n    = blockIdx.y;
    const int oy0  = band * RROWS;

    const float* A = sr + (size_t)n * 3 * PLANE;
    const float* B = hr + (size_t)n * 3 * PLANE;

    // zero smem once: halo entries stay zero forever
    for (int i = t; i < GROWS * WID4; i += NT) cs4[i] = make_float4(0.f, 0.f, 0.f, 0.f);
    for (int i = t; i < GROWS * WIDS; i += NT) cs1[i] = 0.0f;

    float wa[11], wb[11];
    #pragma unroll
    for (int k = 0; k < 11; k++) { wa[k] = 0.0f; wb[k] = 0.0f; }
    float Sa = 0.f, Sb = 0.f, Saa = 0.f, Sbb = 0.f, Sab = 0.f;

    const bool col_ok = (t < CROP);
    int ry  = oy0 - 5;
    int off = (ry + SHAVE) * IMG + (t + SHAVE);

    // ---- warm-up: 10 row inserts ----
    #pragma unroll
    for (int i = 0; i < 10; i++) {
        bool valid = col_ok && (ry >= 0) && (ry < CROP);
        insert_row(A, B, off, valid, wa, wb, Sa, Sb, Saa, Sbb, Sab);
        ry++; off += IMG;
    }
    __syncthreads();

    const float inv121 = 1.0f / 121.0f;
    const float C1 = 6.5025f;
    const float C2 = 58.5225f;

    float acc = 0.0f;

    #pragma unroll
    for (int jb = 0; jb < NBATCH; jb++) {
        // ---- vertical: insert GROWS rows, emit packed colsums ----
        #pragma unroll
        for (int g = 0; g < GROWS; g++) {
            int gy = oy0 + jb * GROWS + g;
            bool valid = col_ok && (ry < CROP);
            insert_row(A, B, off, valid, wa, wb, Sa, Sb, Saa, Sbb, Sab);
            ry++; off += IMG;
            if (col_ok && gy < CROP) {
                int ix = t + 5;
                cs4[Q4(g, ix)] = make_float4(Sa, Sb, Saa, Sbb);
                cs1[Q1(g, ix)] = Sab;
            }
        }
        __syncthreads();

        // ---- horizontal: runs of 8 outputs, sliding windows ----
        if (t < 496) {
            int row = t / 62;             // 0..7
            int run = t % 62;             // 0..61
            int x0  = run * 8;
            int gy  = oy0 + jb * GROWS + row;
            if (gy < CROP) {
                float H0 = 0.f, H1 = 0.f, H2 = 0.f, H3 = 0.f, H4 = 0.f;
                #pragma unroll
                for (int d = 0; d < 11; d++) {
                    float4 q = cs4[Q4(row, x0 + d)];
                    H0 += q.x; H1 += q.y; H2 += q.z; H3 += q.w;
                    H4 += cs1[Q1(row, x0 + d)];
                }
                #pragma unroll
                for (int m = 0; m < 8; m++) {
                    if (x0 + m < CROP) {
                        float mu1 = H0 * inv121;
                        float mu2 = H1 * inv121;
                        float mu1_sq  = mu1 * mu1;
                        float mu2_sq  = mu2 * mu2;
                        float mu1_mu2 = mu1 * mu2;
                        float sig1  = H2 * inv121 - mu1_sq;
                        float sig2  = H3 * inv121 - mu2_sq;
                        float sig12 = H4 * inv121 - mu1_mu2;
                        float num = (2.0f * mu1_mu2 + C1) * (2.0f * sig12 + C2);
                        float den = (mu1_sq + mu2_sq + C1) * (sig1 + sig2 + C2);
                        acc += 1.0f - __fdividef(num, den);
                    }
                    if (m < 7) {
                        float4 qo = cs4[Q4(row, x0 + m)];
                        float4 qn = cs4[Q4(row, x0 + m + 11)];
                        H0 += qn.x - qo.x;
                        H1 += qn.y - qo.y;
                        H2 += qn.z - qo.z;
                        H3 += qn.w - qo.w;
                        H4 += cs1[Q1(row, x0 + m + 11)] - cs1[Q1(row, x0 + m)];
                    }
                }
            }
        }
        __syncthreads();
    }

    // ---- block reduction -> per-block partial ----
    #pragma unroll
    for (int o = 16; o > 0; o >>= 1)
        acc += __shfl_down_sync(0xffffffffu, acc, o);
    int lane = t & 31, warp = t >> 5;
    if (lane == 0) redf[warp] = acc;
    __syncthreads();
    if (warp == 0) {
        float v = (lane < NT / 32) ? redf[lane] : 0.0f;
        #pragma unroll
        for (int o = 16; o > 0; o >>= 1)
            v += __shfl_down_sync(0xffffffffu, v, o);
        if (lane == 0)
            g_part[n * NBANDS + band] = (double)v;
    }

    // ---- last block performs the global reduction ----
    if (t == 0) {
        __threadfence();
        unsigned old = atomicAdd(&g_count, 1u);
        s_last = (old == NBLOCKS - 1) ? 1 : 0;
    }
    __syncthreads();
    if (s_last) {
        double v = (t < NBLOCKS) ? g_part[t] : 0.0;
        #pragma unroll
        for (int o = 16; o > 0; o >>= 1)
            v += __shfl_down_sync(0xffffffffu, v, o);
        if (lane == 0) redd[warp] = v;
        __syncthreads();
        if (warp == 0) {
            double s = (lane < NT / 32) ? redd[lane] : 0.0;
            #pragma unroll
            for (int o = 16; o > 0; o >>= 1)
                s += __shfl_down_sync(0xffffffffu, s, o);
            if (lane == 0) {
                float divisor = 16.0f;
                if (bs_ptr) {
                    int vi = *(const int*)bs_ptr;
                    if (vi > 0 && vi < 100000000) divisor = (float)vi;
                    else {
                        float vf = *(const float*)bs_ptr;
                        if (vf > 0.0f && vf < 1.0e8f) divisor = vf;
                    }
                }
                out[0]  = (float)(s / (double)divisor);
                g_count = 0;   // reset for next graph replay
            }
        }
    }
}

extern "C" void kernel_launch(void* const* d_in, const int* in_sizes, int n_in,
                              void* d_out, int out_size)
{
    const float* sr = (const float*)d_in[0];
    const float* hr = (const float*)d_in[1];
    const void* bs  = (n_in >= 3) ? d_in[2] : nullptr;
    float* out = (float*)d_out;

    cudaFuncSetAttribute(ssim_band_kernel,
                         cudaFuncAttributeMaxDynamicSharedMemorySize, SMEM_BYTES);

    dim3 grid(NBANDS, 16);
    ssim_band_kernel<<<grid, NT, SMEM_BYTES>>>(sr, hr, out, bs);
}

// round 5
// speedup vs baseline: 2.2813x; 1.0073x over previous
#include <cuda_runtime.h>
#include <cuda_bf16.h>

// SSIM loss — band-structured fused kernel, single launch, vectorized smem.
// float4 plane holds (Sa,Sb,Saa,Sbb) column sums, scalar plane holds Sab.
// Vertical 11-tap via register sliding windows; horizontal 11-tap via
// swizzled smem sliding windows in runs of 8 outputs per thread.

#define IMG    512
#define CROP   492
#define SHAVE  10
#define PLANE  (IMG * IMG)

#define NBANDS 16
#define RROWS  32
#define GROWS  8
#define NBATCH (RROWS / GROWS)   // 4
#define WID4   512
#define WIDS   576
#define NT     512
#define NBLOCKS (NBANDS * 16)    // 256

#define SWZ4(i) ((i) ^ (((i) >> 3) & 7))
#define SWZS(i) ((i) + ((i) >> 3))
#define Q4(s, i) ((s) * WID4 + SWZ4(i))
#define Q1(s, i) ((s) * WIDS + SWZS(i))

#define SMEM_BYTES (GROWS * WID4 * 16 + GROWS * WIDS * 4)   // 83968

__device__ double   g_part[NBLOCKS];
__device__ unsigned g_count = 0;

__device__ __forceinline__ void insert_row(
    const float* __restrict__ A, const float* __restrict__ B, int off, bool valid,
    float (&wa)[11], float (&wb)[11],
    float& Sa, float& Sb, float& Saa, float& Sbb, float& Sab)
{
    const float w0 = 65.738f  / 256.0f;
    const float w1 = 129.057f / 256.0f;
    const float w2 = 25.064f  / 256.0f;
    const float inv255 = 1.0f / 255.0f;

    float a = 0.0f, b = 0.0f;
    if (valid) {
        float c0 = __saturatef(A[off]           * inv255);
        float c1 = __saturatef(A[off + PLANE]   * inv255);
        float c2 = __saturatef(A[off + 2*PLANE] * inv255);
        a = w0 * c0 + w1 * c1 + w2 * c2;
        float d0 = __saturatef(B[off]           * inv255);
        float d1 = __saturatef(B[off + PLANE]   * inv255);
        float d2 = __saturatef(B[off + 2*PLANE] * inv255);
        b = w0 * d0 + w1 * d1 + w2 * d2;
    }
    float oa = wa[0], ob = wb[0];
    Sa  += a - oa;
    Sb  += b - ob;
    Saa += a * a - oa * oa;
    Sbb += b * b - ob * ob;
    Sab += a * b - oa * ob;
    #pragma unroll
    for (int k = 0; k < 10; k++) { wa[k] = wa[k + 1]; wb[k] = wb[k + 1]; }
    wa[10] = a; wb[10] = b;
}

__global__ __launch_bounds__(NT, 2)
void ssim_band_kernel(const float* __restrict__ sr, const float* __restrict__ hr,
                      float* __restrict__ out, const void* __restrict__ bs_ptr)
{
    extern __shared__ char smem_raw[];
    float4* cs4 = (float4*)smem_raw;                              // [GROWS][WID4]
    float*  cs1 = (float*)(smem_raw + GROWS * WID4 * 16);          // [GROWS][WIDS]

    __shared__ float  redf[NT / 32];
    __shared__ double redd[NT / 32];
    __shared__ int    s_last;

    const int t    = threadIdx.x;
    const int band = blockIdx.x;
    const int n    = blockIdx.y;
    const int oy0  = band * RROWS;

    const float* A = sr + (size_t)n * 3 * PLANE;
    const float* B = hr + (size_t)n * 3 * PLANE;

    // zero smem once: halo entries stay zero forever
    for (int i = t; i < GROWS * WID4; i += NT) cs4[i] = make_float4(0.f, 0.f, 0.f, 0.f);
    for (int i = t; i < GROWS * WIDS; i += NT) cs1[i] = 0.0f;

    float wa[11], wb[11];
    #pragma unroll
    for (int k = 0; k < 11; k++) { wa[k] = 0.0f; wb[k] = 0.0f; }
    float Sa = 0.f, Sb = 0.f, Saa = 0.f, Sbb = 0.f, Sab = 0.f;

    const bool col_ok = (t < CROP);
    int ry  = oy0 - 5;
    int off = (ry + SHAVE) * IMG + (t + SHAVE);

    // ---- warm-up: 10 row inserts ----
    #pragma unroll
    for (int i = 0; i < 10; i++) {
        bool valid = col_ok && (ry >= 0) && (ry < CROP);
        insert_row(A, B, off, valid, wa, wb, Sa, Sb, Saa, Sbb, Sab);
        ry++; off += IMG;
    }
    __syncthreads();

    const float inv121 = 1.0f / 121.0f;
    const float C1 = 6.5025f;
    const float C2 = 58.5225f;

    float acc = 0.0f;

    #pragma unroll
    for (int jb = 0; jb < NBATCH; jb++) {
        // ---- vertical: insert GROWS rows, emit packed colsums ----
        #pragma unroll
        for (int g = 0; g < GROWS; g++) {
            int gy = oy0 + jb * GROWS + g;
            bool valid = col_ok && (ry < CROP);
            insert_row(A, B, off, valid, wa, wb, Sa, Sb, Saa, Sbb, Sab);
            ry++; off += IMG;
            if (col_ok && gy < CROP) {
                int ix = t + 5;
                cs4[Q4(g, ix)] = make_float4(Sa, Sb, Saa, Sbb);
                cs1[Q1(g, ix)] = Sab;
            }
        }
        __syncthreads();

        // ---- horizontal: runs of 8 outputs, sliding windows ----
        if (t < 496) {
            int row = t / 62;             // 0..7
            int run = t % 62;             // 0..61
            int x0  = run * 8;
            int gy  = oy0 + jb * GROWS + row;
            if (gy < CROP) {
                float H0 = 0.f, H1 = 0.f, H2 = 0.f, H3 = 0.f, H4 = 0.f;
                #pragma unroll
                for (int d = 0; d < 11; d++) {
                    float4 q = cs4[Q4(row, x0 + d)];
                    H0 += q.x; H1 += q.y; H2 += q.z; H3 += q.w;
                    H4 += cs1[Q1(row, x0 + d)];
                }
                #pragma unroll
                for (int m = 0; m < 8; m++) {
                    if (x0 + m < CROP) {
                        float mu1 = H0 * inv121;
                        float mu2 = H1 * inv121;
                        float mu1_sq  = mu1 * mu1;
                        float mu2_sq  = mu2 * mu2;
                        float mu1_mu2 = mu1 * mu2;
                        float sig1  = H2 * inv121 - mu1_sq;
                        float sig2  = H3 * inv121 - mu2_sq;
                        float sig12 = H4 * inv121 - mu1_mu2;
                        float num = (2.0f * mu1_mu2 + C1) * (2.0f * sig12 + C2);
                        float den = (mu1_sq + mu2_sq + C1) * (sig1 + sig2 + C2);
                        acc += 1.0f - __fdividef(num, den);
                    }
                    if (m < 7) {
                        float4 qo = cs4[Q4(row, x0 + m)];
                        float4 qn = cs4[Q4(row, x0 + m + 11)];
                        H0 += qn.x - qo.x;
                        H1 += qn.y - qo.y;
                        H2 += qn.z - qo.z;
                        H3 += qn.w - qo.w;
                        H4 += cs1[Q1(row, x0 + m + 11)] - cs1[Q1(row, x0 + m)];
                    }
                }
            }
        }
        __syncthreads();
    }

    // ---- block reduction -> per-block partial ----
    #pragma unroll
    for (int o = 16; o > 0; o >>= 1)
        acc += __shfl_down_sync(0xffffffffu, acc, o);
    int lane = t & 31, warp = t >> 5;
    if (lane == 0) redf[warp] = acc;
    __syncthreads();
    if (warp == 0) {
        float v = (lane < NT / 32) ? redf[lane] : 0.0f;
        #pragma unroll
        for (int o = 16; o > 0; o >>= 1)
            v += __shfl_down_sync(0xffffffffu, v, o);
        if (lane == 0)
            g_part[n * NBANDS + band] = (double)v;
    }

    // ---- last block performs the global reduction ----
    if (t == 0) {
        __threadfence();
        unsigned old = atomicAdd(&g_count, 1u);
        s_last = (old == NBLOCKS - 1) ? 1 : 0;
    }
    __syncthreads();
    if (s_last) {
        double v = (t < NBLOCKS) ? g_part[t] : 0.0;
        #pragma unroll
        for (int o = 16; o > 0; o >>= 1)
            v += __shfl_down_sync(0xffffffffu, v, o);
        if (lane == 0) redd[warp] = v;
        __syncthreads();
        if (warp == 0) {
            double s = (lane < NT / 32) ? redd[lane] : 0.0;
            #pragma unroll
            for (int o = 16; o > 0; o >>= 1)
                s += __shfl_down_sync(0xffffffffu, s, o);
            if (lane == 0) {
                float divisor = 16.0f;
                if (bs_ptr) {
                    int vi = *(const int*)bs_ptr;
                    if (vi > 0 && vi < 100000000) divisor = (float)vi;
                    else {
                        float vf = *(const float*)bs_ptr;
                        if (vf > 0.0f && vf < 1.0e8f) divisor = vf;
                    }
                }
                out[0]  = (float)(s / (double)divisor);
                g_count = 0;   // reset for next graph replay
            }
        }
    }
}

extern "C" void kernel_launch(void* const* d_in, const int* in_sizes, int n_in,
                              void* d_out, int out_size)
{
    const float* sr = (const float*)d_in[0];
    const float* hr = (const float*)d_in[1];
    const void* bs  = (n_in >= 3) ? d_in[2] : nullptr;
    float* out = (float*)d_out;

    cudaFuncSetAttribute(ssim_band_kernel,
                         cudaFuncAttributeMaxDynamicSharedMemorySize, SMEM_BYTES);

    dim3 grid(NBANDS, 16);
    ssim_band_kernel<<<grid, NT, SMEM_BYTES>>>(sr, hr, out, bs);
}